// round 2
// baseline (speedup 1.0000x reference)
#include <cuda_runtime.h>
#include <cstdint>

// ============================================================================
// Problem constants
// ============================================================================
#define DIN    4096
#define DOUT   12288
#define MROWS  4096            // B*S = 2*2048

#define BM     128
#define BN     128
#define BK     32
#define STAGES 4
#define KT     (DIN / BK)      // 128

#define A_FLOATS   (BM * BK)               // 4096
#define B_FLOATS   (BN * BK)               // 4096
#define STG_FLOATS (A_FLOATS + B_FLOATS)   // 8192
#define SMEM_BYTES (STAGES * STG_FLOATS * 4)  // 131072

// ============================================================================
// Scratch (__device__ globals: allocation-free)
// ============================================================================
__device__ float g_W[(size_t)DOUT * DIN];   // dequantized, tf32-rounded weights
__device__ float g_X[(size_t)MROWS * DIN];  // tf32-rounded activations

// ============================================================================
// PTX helpers (sm_80-baseline only: cp.async + mma.sync tf32)
// ============================================================================
__device__ __forceinline__ uint32_t smem_u32(const void* p) {
    uint32_t a;
    asm("{ .reg .u64 t; cvta.to.shared.u64 t, %1; cvt.u32.u64 %0, t; }" : "=r"(a) : "l"(p));
    return a;
}
__device__ __forceinline__ float rna_tf32(float v) {
    uint32_t r;
    asm("cvt.rna.tf32.f32 %0, %1;" : "=r"(r) : "f"(v));
    return __uint_as_float(r);
}

#define CP_ASYNC16(dst, src) \
    asm volatile("cp.async.cg.shared.global [%0], [%1], 16;" :: "r"(dst), "l"(src) : "memory")
#define CP_COMMIT() asm volatile("cp.async.commit_group;" ::: "memory")
#define CP_WAIT2()  asm volatile("cp.async.wait_group 2;" ::: "memory")

__device__ __forceinline__ void mma_tf32(float c[4], uint32_t a0, uint32_t a1, uint32_t a2,
                                         uint32_t a3, uint32_t b0, uint32_t b1) {
    asm volatile(
        "mma.sync.aligned.m16n8k8.row.col.f32.tf32.tf32.f32 "
        "{%0,%1,%2,%3}, {%4,%5,%6,%7}, {%8,%9}, {%0,%1,%2,%3};"
        : "+f"(c[0]), "+f"(c[1]), "+f"(c[2]), "+f"(c[3])
        : "r"(a0), "r"(a1), "r"(a2), "r"(a3), "r"(b0), "r"(b1));
}

// ============================================================================
// Prep: RNA-round both operands to tf32 (kills truncation bias); dequant W
// ============================================================================
__global__ void prep_x_kernel(const float4* __restrict__ x, float4* __restrict__ out) {
    int i = blockIdx.x * blockDim.x + threadIdx.x;
    float4 v = x[i];
    v.x = rna_tf32(v.x); v.y = rna_tf32(v.y);
    v.z = rna_tf32(v.z); v.w = rna_tf32(v.w);
    out[i] = v;
}

__global__ void prep_w_kernel(const float4* __restrict__ peso, const float* __restrict__ escala,
                              float4* __restrict__ out) {
    int i = blockIdx.x * blockDim.x + threadIdx.x;
    int col4 = i & (DIN / 4 - 1);     // float4 column index
    int row  = i >> 10;               // i / (DIN/4)
    float s = __ldg(&escala[(row >> 7) * (DIN / 128) + (col4 >> 5)]);
    float4 v = peso[i];
    v.x = rna_tf32(v.x * s); v.y = rna_tf32(v.y * s);
    v.z = rna_tf32(v.z * s); v.w = rna_tf32(v.w * s);
    out[i] = v;
}

// ============================================================================
// GEMM: C[m,n] = sum_k X[m,k] * W[n,k]
//   128x128 CTA tile, BK=32, 4-stage cp.async pipeline,
//   8 warps (2 M x 4 N), warp tile 64x32, mma.sync m16n8k8 tf32.
// Smem layout per tile row: 32 floats (128B), 16B chunks XOR-swizzled by row&7.
// ============================================================================
__global__ void __launch_bounds__(256, 1)
gemm_tf32_kernel(const float* __restrict__ gA,   // g_X [MROWS, DIN]
                 const float* __restrict__ gB,   // g_W [DOUT, DIN]
                 float* __restrict__ out) {      // [MROWS, DOUT]
    extern __shared__ float smem[];

    const int tid    = threadIdx.x;
    const int wid    = tid >> 5;
    const int lane   = tid & 31;
    const int group  = lane >> 2;     // 0..7
    const int tig    = lane & 3;      // 0..3
    const int warp_m = wid >> 2;      // 0..1
    const int warp_n = wid & 3;       // 0..3

    const int m0 = blockIdx.y * BM;
    const int n0 = blockIdx.x * BN;

    // cp.async mapping: each thread moves 4 rows x 16B for A and for B
    const int ld_row = tid >> 3;      // 0..31
    const int ld_ch  = tid & 7;       // 0..7 (16B chunk within 128B row)

    const uint32_t smem_base = smem_u32(smem);

    // ---- stage loader ----
    auto load_stage = [&](int s, int kt) {
        const uint32_t As = smem_base + (uint32_t)(s * STG_FLOATS) * 4u;
        const uint32_t Bs = As + A_FLOATS * 4u;
        const int k0 = kt * BK;
#pragma unroll
        for (int r = 0; r < 4; r++) {
            const int rr = ld_row + r * 32;
            const int sw = ((ld_ch ^ (rr & 7)) << 2);       // swizzled float offset
            const float* srcA = gA + (size_t)(m0 + rr) * DIN + k0 + ld_ch * 4;
            CP_ASYNC16(As + (uint32_t)(rr * 32 + sw) * 4u, srcA);
            const float* srcB = gB + (size_t)(n0 + rr) * DIN + k0 + ld_ch * 4;
            CP_ASYNC16(Bs + (uint32_t)(rr * 32 + sw) * 4u, srcB);
        }
    };

    float c[4][4][4];
#pragma unroll
    for (int i = 0; i < 4; i++)
#pragma unroll
        for (int j = 0; j < 4; j++)
#pragma unroll
            for (int r = 0; r < 4; r++) c[i][j][r] = 0.0f;

    // ---- prologue: fill STAGES-1 stages ----
#pragma unroll
    for (int s = 0; s < STAGES - 1; s++) {
        load_stage(s, s);
        CP_COMMIT();
    }

    // ---- main loop ----
    for (int kt = 0; kt < KT; kt++) {
        CP_WAIT2();
        __syncthreads();

        // prefetch stage kt+3 (overwrites slot consumed at kt-1; safe after sync)
        if (kt + STAGES - 1 < KT) load_stage((kt + STAGES - 1) & (STAGES - 1), kt + STAGES - 1);
        CP_COMMIT();

        const int s = kt & (STAGES - 1);
        const float* As = smem + s * STG_FLOATS;
        const float* Bs = As + A_FLOATS;

#pragma unroll
        for (int ks = 0; ks < 4; ks++) {            // 4 x k8 steps
            const int ch0 = ks * 2;                 // 16B chunk of k = ks*8 + [0,4)
            uint32_t a[4][4], b[4][2];
#pragma unroll
            for (int mf = 0; mf < 4; mf++) {
                const int m = warp_m * 64 + mf * 16 + group;
                const float* pr = As + m * 32;
                const int x0 = (((ch0)     ^ (m & 7)) << 2) + tig;
                const int x1 = (((ch0 + 1) ^ (m & 7)) << 2) + tig;
                a[mf][0] = __float_as_uint(pr[x0]);
                a[mf][1] = __float_as_uint(pr[8 * 32 + x0]);
                a[mf][2] = __float_as_uint(pr[x1]);
                a[mf][3] = __float_as_uint(pr[8 * 32 + x1]);
            }
#pragma unroll
            for (int nf = 0; nf < 4; nf++) {
                const int n = warp_n * 32 + nf * 8 + group;
                const float* pr = Bs + n * 32;
                const int x0 = (((ch0)     ^ (n & 7)) << 2) + tig;
                const int x1 = (((ch0 + 1) ^ (n & 7)) << 2) + tig;
                b[nf][0] = __float_as_uint(pr[x0]);
                b[nf][1] = __float_as_uint(pr[x1]);
            }
#pragma unroll
            for (int mf = 0; mf < 4; mf++)
#pragma unroll
                for (int nf = 0; nf < 4; nf++)
                    mma_tf32(c[mf][nf], a[mf][0], a[mf][1], a[mf][2], a[mf][3],
                             b[nf][0], b[nf][1]);
        }
    }

    // ---- epilogue: direct float2 global stores ----
#pragma unroll
    for (int mf = 0; mf < 4; mf++) {
        const int m = m0 + warp_m * 64 + mf * 16 + group;
#pragma unroll
        for (int nf = 0; nf < 4; nf++) {
            const int n = n0 + warp_n * 32 + nf * 8 + tig * 2;
            float2 v0 = make_float2(c[mf][nf][0], c[mf][nf][1]);
            float2 v1 = make_float2(c[mf][nf][2], c[mf][nf][3]);
            *reinterpret_cast<float2*>(&out[(size_t)m * DOUT + n])       = v0;
            *reinterpret_cast<float2*>(&out[(size_t)(m + 8) * DOUT + n]) = v1;
        }
    }
}

// ============================================================================
// Host launch
// ============================================================================
extern "C" void kernel_launch(void* const* d_in, const int* in_sizes, int n_in,
                              void* d_out, int out_size) {
    const float* x      = (const float*)d_in[0];
    const float* peso   = (const float*)d_in[1];
    const float* escala = (const float*)d_in[2];
    float* out          = (float*)d_out;

    float *gX = nullptr, *gW = nullptr;
    cudaGetSymbolAddress((void**)&gX, g_X);
    cudaGetSymbolAddress((void**)&gW, g_W);

    prep_x_kernel<<<(MROWS * DIN / 4) / 256, 256>>>((const float4*)x, (float4*)gX);
    prep_w_kernel<<<(DOUT * DIN / 4) / 256, 256>>>((const float4*)peso, escala, (float4*)gW);

    static bool attr_set = false;
    if (!attr_set) {
        cudaFuncSetAttribute(gemm_tf32_kernel, cudaFuncAttributeMaxDynamicSharedMemorySize,
                             SMEM_BYTES);
        attr_set = true;
    }

    dim3 grid(DOUT / BN, MROWS / BM);   // 96 x 32
    gemm_tf32_kernel<<<grid, 256, SMEM_BYTES>>>(gX, gW, out);
}

// round 3
// speedup vs baseline: 2.5778x; 2.5778x over previous
#include <cuda_runtime.h>
#include <cuda.h>
#include <cuda_fp16.h>
#include <cstdint>

// ============================================================================
// Problem constants
// ============================================================================
#define DIN    4096
#define DOUT   12288
#define MROWS  4096

#define BM     256
#define BN     128
#define BK     64               // halves per stage-k = 128 bytes per row
#define STAGES 4
#define KT     (DIN / BK)       // 64

#define A_BYTES     (BM * 128)              // 32768
#define B_BYTES     (BN * 128)              // 16384
#define STAGE_BYTES (A_BYTES + B_BYTES)     // 49152
#define SMEM_DATA0  1024
#define SMEM_TOTAL  (SMEM_DATA0 + STAGES * STAGE_BYTES)   // 197632

#define MBAR_FULL(s)  ((s) * 16)
#define MBAR_EMPTY(s) ((s) * 16 + 8)

#define NWARPS_C 16          // compute warps
#define NTHREADS (NWARPS_C * 32 + 32)   // +1 producer warp = 544

// ============================================================================
// Scratch: fp16 operands (dequantized W, converted X)
// ============================================================================
__device__ __half g_W16[(size_t)DOUT * DIN];   // 96 MB
__device__ __half g_X16[(size_t)MROWS * DIN];  // 32 MB

// ============================================================================
// PTX helpers (all plain-sm_103-legal: TMA, mbarrier, ldmatrix, mma.sync)
// ============================================================================
__device__ __forceinline__ uint32_t smem_u32(const void* p) {
    uint32_t a;
    asm("{ .reg .u64 t; cvta.to.shared.u64 t, %1; cvt.u32.u64 %0, t; }" : "=r"(a) : "l"(p));
    return a;
}
__device__ __forceinline__ uint32_t elect_one() {
    uint32_t p;
    asm volatile("{ .reg .pred p; elect.sync _|p, 0xFFFFFFFF; selp.b32 %0, 1, 0, p; }" : "=r"(p));
    return p;
}

#define MBAR_INIT(addr, cnt) \
    asm volatile("mbarrier.init.shared.b64 [%0], %1;" :: "r"(addr), "r"(cnt) : "memory")
#define MBAR_EXPECT_TX(addr, bytes) \
    asm volatile("mbarrier.arrive.expect_tx.shared.b64 _, [%0], %1;" :: "r"(addr), "r"(bytes) : "memory")
#define MBAR_ARRIVE(addr) \
    asm volatile("mbarrier.arrive.shared.b64 _, [%0];" :: "r"(addr) : "memory")

#define MBAR_WAIT(mbar_addr, phase_parity) do {                                         \
    uint32_t _mbar = (uint32_t)(mbar_addr);                                             \
    uint32_t _par  = (uint32_t)(phase_parity);                                          \
    uint32_t _done;                                                                     \
    asm volatile("{\n\t.reg .pred p;\n\t"                                               \
        "mbarrier.try_wait.parity.acquire.cta.shared::cta.b64 p, [%1], %2;\n\t"         \
        "selp.b32 %0, 1, 0, p;\n\t}"                                                    \
        : "=r"(_done) : "r"(_mbar), "r"(_par) : "memory");                              \
    if (!_done) {                                                                       \
        asm volatile("{\n\t.reg .pred P1;\n\t"                                          \
            "WAIT_LOOP_%=:\n\t"                                                         \
            "mbarrier.try_wait.parity.acquire.cta.shared::cta.b64 P1, [%0], %1, 0x989680;\n\t" \
            "@P1 bra.uni WAIT_DONE_%=;\n\t"                                             \
            "bra.uni WAIT_LOOP_%=;\n\t"                                                 \
            "WAIT_DONE_%=:\n\t}"                                                        \
            :: "r"(_mbar), "r"(_par) : "memory");                                       \
    }                                                                                   \
} while (0)

#define TMA_LOAD2D(smem, map, cx, cy, mbar)                                             \
    asm volatile("cp.async.bulk.tensor.2d.shared::cta.global.tile.mbarrier::complete_tx::bytes " \
                 "[%0], [%1, {%2, %3}], [%4];"                                          \
                 :: "r"(smem), "l"(map), "r"(cx), "r"(cy), "r"(mbar) : "memory")

#define LDSM_X4(r0, r1, r2, r3, addr)                                                   \
    asm volatile("ldmatrix.sync.aligned.m8n8.x4.shared.b16 {%0,%1,%2,%3}, [%4];"        \
                 : "=r"(r0), "=r"(r1), "=r"(r2), "=r"(r3) : "r"(addr))

__device__ __forceinline__ void mma_f16(float c[4], uint32_t a0, uint32_t a1, uint32_t a2,
                                        uint32_t a3, uint32_t b0, uint32_t b1) {
    asm volatile(
        "mma.sync.aligned.m16n8k16.row.col.f32.f16.f16.f32 "
        "{%0,%1,%2,%3}, {%4,%5,%6,%7}, {%8,%9}, {%0,%1,%2,%3};"
        : "+f"(c[0]), "+f"(c[1]), "+f"(c[2]), "+f"(c[3])
        : "r"(a0), "r"(a1), "r"(a2), "r"(a3), "r"(b0), "r"(b1));
}

// ============================================================================
// Prep: convert x -> fp16; dequant w*scale -> fp16 (8 floats / thread)
// ============================================================================
__device__ __forceinline__ uint32_t h2bits(float a, float b) {
    __half2 h = __floats2half2_rn(a, b);
    return *reinterpret_cast<uint32_t*>(&h);
}

__global__ void prep_x_kernel(const float4* __restrict__ x, uint4* __restrict__ out) {
    int i = blockIdx.x * blockDim.x + threadIdx.x;
    float4 v0 = x[2 * i], v1 = x[2 * i + 1];
    uint4 u;
    u.x = h2bits(v0.x, v0.y); u.y = h2bits(v0.z, v0.w);
    u.z = h2bits(v1.x, v1.y); u.w = h2bits(v1.z, v1.w);
    out[i] = u;
}

__global__ void prep_w_kernel(const float4* __restrict__ peso, const float* __restrict__ escala,
                              uint4* __restrict__ out) {
    int i = blockIdx.x * blockDim.x + threadIdx.x;
    int e   = i << 3;                 // first element index
    int row = e >> 12;                // / DIN
    int col = e & (DIN - 1);
    float s = __ldg(&escala[(row >> 7) * (DIN / 128) + (col >> 7)]);
    float4 v0 = peso[2 * i], v1 = peso[2 * i + 1];
    uint4 u;
    u.x = h2bits(v0.x * s, v0.y * s); u.y = h2bits(v0.z * s, v0.w * s);
    u.z = h2bits(v1.x * s, v1.y * s); u.w = h2bits(v1.z * s, v1.w * s);
    out[i] = u;
}

// ============================================================================
// GEMM: C[m,n] = sum_k X[m,k] * W[n,k]   (fp16 in, fp32 accum/out)
//   CTA tile 256x128, BK=64, 4-stage TMA pipeline, SW128 tensormaps.
//   16 compute warps (4M x 4N, warp tile 64x32) + 1 TMA producer warp.
// ============================================================================
__global__ void __launch_bounds__(NTHREADS, 1)
gemm_f16_kernel(const __grid_constant__ CUtensorMap tmA,
                const __grid_constant__ CUtensorMap tmB,
                float* __restrict__ out) {
    extern __shared__ char smem[];
    const uint32_t sb = smem_u32(smem);
    const int tid  = threadIdx.x;
    const int wid  = tid >> 5;
    const int lane = tid & 31;

    const int m0 = blockIdx.y * BM;
    const int n0 = blockIdx.x * BN;

    if (tid == 0) {
        for (int s = 0; s < STAGES; s++) {
            MBAR_INIT(sb + MBAR_FULL(s), 1);
            MBAR_INIT(sb + MBAR_EMPTY(s), NWARPS_C);
        }
    }
    __syncthreads();

    if (wid == NWARPS_C) {
        // ---------------- TMA producer warp ----------------
        if (elect_one()) {
            int s = 0, ph = 1;               // first empty-wait passes immediately
            for (int kt = 0; kt < KT; kt++) {
                MBAR_WAIT(sb + MBAR_EMPTY(s), ph);
                MBAR_EXPECT_TX(sb + MBAR_FULL(s), STAGE_BYTES);
                const uint32_t stg = sb + SMEM_DATA0 + s * STAGE_BYTES;
                TMA_LOAD2D(stg,           &tmA, kt * BK, m0, sb + MBAR_FULL(s));
                TMA_LOAD2D(stg + A_BYTES, &tmB, kt * BK, n0, sb + MBAR_FULL(s));
                if (++s == STAGES) { s = 0; ph ^= 1; }
            }
        }
        return;
    }

    // ---------------- compute warps ----------------
    const int warp_m = wid & 3;          // 0..3 -> M offset 64*warp_m
    const int warp_n = wid >> 2;         // 0..3 -> N offset 32*warp_n
    const int q = lane >> 3;             // ldmatrix quad
    const int iq = lane & 7;

    // ldmatrix lane-address components (row within fragment, chunk select)
    const int a_rif = ((q & 1) << 3) + iq;    // 0..15
    const int a_csel = q >> 1;                // 0/1
    const int b_rif = ((q >> 1) << 3) + iq;   // 0..15
    const int b_csel = q & 1;                 // 0/1

    float c[4][4][4];
#pragma unroll
    for (int mf = 0; mf < 4; mf++)
#pragma unroll
        for (int nf = 0; nf < 4; nf++)
#pragma unroll
            for (int r = 0; r < 4; r++) c[mf][nf][r] = 0.0f;

    int s = 0, ph = 0;
    for (int kt = 0; kt < KT; kt++) {
        MBAR_WAIT(sb + MBAR_FULL(s), ph);
        const uint32_t As = sb + SMEM_DATA0 + s * STAGE_BYTES;
        const uint32_t Bs = As + A_BYTES;

        // per-stage lane base addresses (row*128, plus row&7 for swizzle)
        uint32_t a_base[4], a_sw[4];
#pragma unroll
        for (int mf = 0; mf < 4; mf++) {
            int row = warp_m * 64 + mf * 16 + a_rif;
            a_base[mf] = As + row * 128;
            a_sw[mf]   = (uint32_t)(row & 7);
        }
        uint32_t b_base[2], b_sw[2];
#pragma unroll
        for (int p = 0; p < 2; p++) {
            int row = warp_n * 32 + p * 16 + b_rif;
            b_base[p] = Bs + row * 128;
            b_sw[p]   = (uint32_t)(row & 7);
        }

#pragma unroll
        for (int ks = 0; ks < 4; ks++) {       // 4 x k16 per stage
            uint32_t a[4][4], b[4][2];
#pragma unroll
            for (int mf = 0; mf < 4; mf++) {
                uint32_t ch = (uint32_t)(2 * ks + a_csel);
                uint32_t addr = a_base[mf] + ((ch ^ a_sw[mf]) << 4);
                LDSM_X4(a[mf][0], a[mf][1], a[mf][2], a[mf][3], addr);
            }
#pragma unroll
            for (int p = 0; p < 2; p++) {
                uint32_t ch = (uint32_t)(2 * ks + b_csel);
                uint32_t addr = b_base[p] + ((ch ^ b_sw[p]) << 4);
                LDSM_X4(b[2 * p][0], b[2 * p][1], b[2 * p + 1][0], b[2 * p + 1][1], addr);
            }
#pragma unroll
            for (int mf = 0; mf < 4; mf++)
#pragma unroll
                for (int nf = 0; nf < 4; nf++)
                    mma_f16(c[mf][nf], a[mf][0], a[mf][1], a[mf][2], a[mf][3],
                            b[nf][0], b[nf][1]);
        }

        __syncwarp();
        if (lane == 0) MBAR_ARRIVE(sb + MBAR_EMPTY(s));
        if (++s == STAGES) { s = 0; ph ^= 1; }
    }

    // ---------------- epilogue: direct float2 stores ----------------
    const int g   = lane >> 2;
    const int tig = lane & 3;
#pragma unroll
    for (int mf = 0; mf < 4; mf++) {
        const int m = m0 + warp_m * 64 + mf * 16 + g;
#pragma unroll
        for (int nf = 0; nf < 4; nf++) {
            const int n = n0 + warp_n * 32 + nf * 8 + tig * 2;
            *reinterpret_cast<float2*>(&out[(size_t)m * DOUT + n]) =
                make_float2(c[mf][nf][0], c[mf][nf][1]);
            *reinterpret_cast<float2*>(&out[(size_t)(m + 8) * DOUT + n]) =
                make_float2(c[mf][nf][2], c[mf][nf][3]);
        }
    }
}

// ============================================================================
// Host launch
// ============================================================================
typedef CUresult (*PFN_encodeTiled)(CUtensorMap*, CUtensorMapDataType, cuuint32_t, void*,
                                    const cuuint64_t*, const cuuint64_t*, const cuuint32_t*,
                                    const cuuint32_t*, CUtensorMapInterleave, CUtensorMapSwizzle,
                                    CUtensorMapL2promotion, CUtensorMapFloatOOBfill);

static PFN_encodeTiled get_encode_fn() {
    void* fn = nullptr;
#if CUDART_VERSION >= 12050
    cudaDriverEntryPointQueryResult qr;
    cudaGetDriverEntryPointByVersion("cuTensorMapEncodeTiled", &fn, 12000, cudaEnableDefault, &qr);
#else
    cudaGetDriverEntryPoint("cuTensorMapEncodeTiled", &fn, cudaEnableDefault);
#endif
    return (PFN_encodeTiled)fn;
}

static void encode_2d_f16(PFN_encodeTiled enc, CUtensorMap* tm, void* ptr,
                          uint64_t d0, uint64_t d1, uint32_t b0, uint32_t b1) {
    cuuint64_t dims[2]    = {d0, d1};
    cuuint64_t strides[1] = {d0 * sizeof(__half)};
    cuuint32_t box[2]     = {b0, b1};
    cuuint32_t es[2]      = {1, 1};
    enc(tm, CU_TENSOR_MAP_DATA_TYPE_FLOAT16, 2, ptr, dims, strides, box, es,
        CU_TENSOR_MAP_INTERLEAVE_NONE, CU_TENSOR_MAP_SWIZZLE_128B,
        CU_TENSOR_MAP_L2_PROMOTION_L2_128B, CU_TENSOR_MAP_FLOAT_OOB_FILL_NONE);
}

extern "C" void kernel_launch(void* const* d_in, const int* in_sizes, int n_in,
                              void* d_out, int out_size) {
    const float* x      = (const float*)d_in[0];
    const float* peso   = (const float*)d_in[1];
    const float* escala = (const float*)d_in[2];
    float* out          = (float*)d_out;

    __half *gX = nullptr, *gW = nullptr;
    cudaGetSymbolAddress((void**)&gX, g_X16);
    cudaGetSymbolAddress((void**)&gW, g_W16);

    prep_x_kernel<<<(MROWS * DIN / 8) / 256, 256>>>((const float4*)x, (uint4*)gX);
    prep_w_kernel<<<(DOUT * DIN / 8) / 256, 256>>>((const float4*)peso, escala, (uint4*)gW);

    PFN_encodeTiled enc = get_encode_fn();
    CUtensorMap tmA, tmB;
    encode_2d_f16(enc, &tmA, gX, DIN, MROWS, BK, BM);   // box 64x256
    encode_2d_f16(enc, &tmB, gW, DIN, DOUT,  BK, BN);   // box 64x128

    static bool attr_set = false;
    if (!attr_set) {
        cudaFuncSetAttribute(gemm_f16_kernel, cudaFuncAttributeMaxDynamicSharedMemorySize,
                             SMEM_TOTAL);
        attr_set = true;
    }

    dim3 grid(DOUT / BN, MROWS / BM);   // 96 x 16
    gemm_f16_kernel<<<grid, NTHREADS, SMEM_TOTAL>>>(tmA, tmB, out);
}